// round 16
// baseline (speedup 1.0000x reference)
#include <cuda_runtime.h>
#include <cuda_fp16.h>
#include <cstdint>

#define BNR    1600
#define HD     256
#define SEQ    64
#define NSTEPS 10
#define MT     17          /* M groups of 96 rows */
#define MROWS  96
#define NCTA   (MT * 8)    /* 136 CTAs, one wave on 148 SMs */

// ------------------------- static device scratch --------------------------
__device__ uint32_t g_xw  [BNR * SEQ * 128];    // x fp16 [m][t][128w]
__device__ uint32_t g_h0buf[2][BNR * 128];
__device__ uint32_t g_h1buf[2][BNR * 128];
__device__ uint32_t g_htw [BNR * 128];          // LN output fp16
__device__ float    g_hid [BNR * 512];
__device__ uint32_t g_Wre0[1024 * 256];         // fp16, rows (j*4+g), k=[Wih|Whh]
__device__ uint32_t g_Wre1[1024 * 256];
__device__ float    g_bre0[1024];
__device__ float    g_bre1[1024];
__device__ uint32_t g_Wh1 [512 * 128];          // heads layer1 weights fp16
__device__ float    g_bh1 [512];
__device__ unsigned g_grpCnt[MT * 32];          // per-group barrier (128B stride)
__device__ unsigned g_grpGen[MT * 32];

// ------------------------------ helpers -----------------------------------
__device__ __forceinline__ void mma_f16(float* d, const uint32_t* a,
                                        uint32_t b0, uint32_t b1) {
    asm volatile(
        "mma.sync.aligned.m16n8k16.row.col.f32.f16.f16.f32 "
        "{%0,%1,%2,%3}, {%4,%5,%6,%7}, {%8,%9}, {%0,%1,%2,%3};"
        : "+f"(d[0]), "+f"(d[1]), "+f"(d[2]), "+f"(d[3])
        : "r"(a[0]), "r"(a[1]), "r"(a[2]), "r"(a[3]), "r"(b0), "r"(b1));
}
__device__ __forceinline__ void ldm_x4(uint32_t& r0, uint32_t& r1,
                                       uint32_t& r2, uint32_t& r3,
                                       uint32_t addr) {
    asm volatile("ldmatrix.sync.aligned.m8n8.x4.shared.b16 {%0,%1,%2,%3}, [%4];"
                 : "=r"(r0), "=r"(r1), "=r"(r2), "=r"(r3) : "r"(addr));
}
__device__ __forceinline__ float tanha(float x) {
    float r;
    asm("tanh.approx.f32 %0, %1;" : "=f"(r) : "f"(x));
    return r;
}
__device__ __forceinline__ float sigf(float x) {
    return fmaf(tanha(0.5f * x), 0.5f, 0.5f);
}
__device__ __forceinline__ void cpa16(uint32_t saddr, const void* g, int sz) {
    asm volatile("cp.async.cg.shared.global [%0], [%1], 16, %2;"
                 :: "r"(saddr), "l"(g), "r"(sz));
}
#define CP_COMMIT() asm volatile("cp.async.commit_group;")

// per-group barrier body (no leading syncthreads) — pure spin, no nanosleep
__device__ __forceinline__ void gbar_body(int grp) {
    if (threadIdx.x == 0) {
        __threadfence();
        unsigned* cnt = &g_grpCnt[grp * 32];
        unsigned* gen = &g_grpGen[grp * 32];
        unsigned g = *(volatile unsigned*)gen;
        if (atomicAdd(cnt, 1u) == 7u) {
            *(volatile unsigned*)cnt = 0u;
            __threadfence();
            atomicExch(gen, g + 1);
        } else {
            while (*(volatile unsigned*)gen == g) { }
        }
        __threadfence();
    }
    __syncthreads();
}
// full barrier (leading sync) — use after phases NOT ending in __syncthreads
__device__ __forceinline__ void gbar(int grp) {
    __syncthreads();
    gbar_body(grp);
}
// no-leading-sync barrier — safe only right after a phase ending in __syncthreads
__device__ __forceinline__ void gbar_ns(int grp) {
    gbar_body(grp);
}

// ------------------------------ setup kernels -----------------------------
__global__ void transpose_kernel(const float* __restrict__ x) {
    int id = blockIdx.x * blockDim.x + threadIdx.x;
    if (id >= BNR * SEQ * 32) return;
    int w8 = id & 31;
    int t  = (id >> 5) & 63;
    int m  = id >> 11;
    int b  = m / 100;
    int n  = m - b * 100;
    const float4* src = (const float4*)x + ((((long)(b * SEQ + t) * 100 + n) * 64) + 2 * w8);
    float4 v0 = src[0], v1 = src[1];
    __half2 h0 = __floats2half2_rn(v0.x, v0.y);
    __half2 h1 = __floats2half2_rn(v0.z, v0.w);
    __half2 h2 = __floats2half2_rn(v1.x, v1.y);
    __half2 h3 = __floats2half2_rn(v1.z, v1.w);
    uint4 o;
    o.x = *(uint32_t*)&h0; o.y = *(uint32_t*)&h1;
    o.z = *(uint32_t*)&h2; o.w = *(uint32_t*)&h3;
    ((uint4*)g_xw)[((long)m * SEQ + t) * 32 + w8] = o;
}

__global__ void rearr_w_kernel(const float* __restrict__ Wih,
                               const float* __restrict__ Whh,
                               const float* __restrict__ bih,
                               const float* __restrict__ bhh,
                               uint32_t* __restrict__ Wre,
                               float* __restrict__ bre) {
    int id = blockIdx.x * 256 + threadIdx.x;
    if (id >= 1024 * 256) return;
    int nre = id >> 8, kw = id & 255;
    int j = nre >> 2, g = nre & 3;
    int srow = g * 256 + j;
    int k = kw * 2;
    float v0, v1;
    if (k < 256) { v0 = Wih[srow * 256 + k];       v1 = Wih[srow * 256 + k + 1]; }
    else         { v0 = Whh[srow * 256 + k - 256]; v1 = Whh[srow * 256 + k - 255]; }
    __half2 h = __floats2half2_rn(v0, v1);
    Wre[id] = *(uint32_t*)&h;
    if (kw == 0) bre[nre] = bih[srow] + bhh[srow];
}

__global__ void rearr_h1_kernel(const float* __restrict__ cw1, const float* __restrict__ cb1,
                                const float* __restrict__ sw1, const float* __restrict__ sb1,
                                const float* __restrict__ lw1, const float* __restrict__ lb1) {
    int id = blockIdx.x * 256 + threadIdx.x;
    if (id >= 512 * 128) return;
    int row = id >> 7, kw = id & 127;
    int k = kw * 2;
    const float* w; float b;
    if (row < 128)      { w = cw1 + row * 256;         b = cb1[row]; }
    else if (row < 256) { w = sw1 + (row - 128) * 256; b = sb1[row - 128]; }
    else                { w = lw1 + (row - 256) * 256; b = lb1[row - 256]; }
    __half2 h = __floats2half2_rn(w[k], w[k + 1]);
    g_Wh1[id] = *(uint32_t*)&h;
    if (kw == 0) g_bh1[row] = b;
}

__global__ void zero_state_kernel() {
    int id = blockIdx.x * blockDim.x + threadIdx.x;
    if (id < BNR * 128) { g_h0buf[0][id] = 0u; g_h1buf[0][id] = 0u; }
    if (id < MT * 32) { g_grpCnt[id] = 0u; g_grpGen[id] = 0u; }
}

// ---------------------------------------------------------------------------
// smem: 4 stages x (A 128x36w + B 128x36w) + biases + 2 h-stages + W2 cache
#define STG_W   9216
#define STG_B   (STG_W * 4)
#define BOF_B   (4608 * 4)
#define BIAS_W  (4 * STG_W)
#define HS0_W   (BIAS_W + 320)            /* __half hs0[96*40] = 1920 words */
#define HS1_W   (HS0_W + 1920)
#define W2S_W   (HS1_W + 1920)            /* layer-2 weights 4864f + 22 bias */
#define PSMEM   ((W2S_W + 4896) * 4)
#define ROWB    144                        /* 36 words * 4 bytes */

// ---------------- shared epilogue helper (per-warp, writes hs) -------------
__device__ __forceinline__ void lstm_epi(
    const float acc[3][4][4], const float* biasS, float* cReg, __half* hs,
    int wm, int wn, int g4, int t4)
{
    const bool oddl = (t4 & 1);
    const unsigned FULL = 0xffffffffu;
#pragma unroll
    for (int mf = 0; mf < 3; ++mf) {
#pragma unroll
        for (int nf = 0; nf < 4; ++nf) {
            float c0v = acc[mf][nf][0], c1v = acc[mf][nf][1];
            float c2v = acc[mf][nf][2], c3v = acc[mf][nf][3];
            float x0 = __shfl_xor_sync(FULL, c0v, 1);
            float x1 = __shfl_xor_sync(FULL, c1v, 1);
            float x2 = __shfl_xor_sync(FULL, c2v, 1);
            float x3 = __shfl_xor_sync(FULL, c3v, 1);
            float gi, gf, gg, go; int rloc;
            if (!oddl) { gi = c0v; gf = c1v; gg = x0;  go = x1;  rloc = g4; }
            else       { gi = x2;  gf = x3;  gg = c2v; go = c3v; rloc = g4 + 8; }
            int rowloc = wm * 48 + mf * 16 + rloc;       // 0..95
            int jl = wn * 8 + nf * 2 + (t4 >> 1);        // 0..31
            gi += biasS[jl * 4 + 0];
            gf += biasS[jl * 4 + 1];
            gg += biasS[jl * 4 + 2];
            go += biasS[jl * 4 + 3];
            float cold = cReg[mf * 4 + nf];
            float cn = sigf(gf) * cold + sigf(gi) * tanha(gg);
            float hn = sigf(go) * tanha(cn);
            cReg[mf * 4 + nf] = cn;
            hs[rowloc * 40 + jl] = __float2half_rn(hn);
        }
    }
}

// ---------------- compute one K-chunk (cell: 4 nf) --------------------------
__device__ __forceinline__ void chunk_mma(
    float acc[3][4][4], uint32_t aPre, uint32_t bPre, int st)
{
#pragma unroll
    for (int ks = 0; ks < 32; ks += 8) {
        uint32_t af[3][4], b0[4], b1[4];
        uint32_t ab = aPre + st * STG_B + ks * 4;
        uint32_t bb = bPre + st * STG_B + ks * 4;
        ldm_x4(af[0][0], af[0][1], af[0][2], af[0][3], ab);
        ldm_x4(af[1][0], af[1][1], af[1][2], af[1][3], ab + 16 * ROWB);
        ldm_x4(af[2][0], af[2][1], af[2][2], af[2][3], ab + 32 * ROWB);
        ldm_x4(b0[0], b1[0], b0[1], b1[1], bb);
        ldm_x4(b0[2], b1[2], b0[3], b1[3], bb + 16 * ROWB);
#pragma unroll
        for (int mf = 0; mf < 3; ++mf)
#pragma unroll
            for (int nf = 0; nf < 4; ++nf)
                mma_f16(acc[mf][nf], af[mf], b0[nf], b1[nf]);
    }
}

// ---------------- compute one K-chunk (heads1: 2 nf) ------------------------
__device__ __forceinline__ void chunk_mma_h1(
    float acc[3][2][4], uint32_t aPre, uint32_t bPre, int st)
{
#pragma unroll
    for (int ks = 0; ks < 32; ks += 8) {
        uint32_t af[3][4], b0[2], b1[2];
        uint32_t ab = aPre + st * STG_B + ks * 4;
        uint32_t bb = bPre + st * STG_B + ks * 4;
        ldm_x4(af[0][0], af[0][1], af[0][2], af[0][3], ab);
        ldm_x4(af[1][0], af[1][1], af[1][2], af[1][3], ab + 16 * ROWB);
        ldm_x4(af[2][0], af[2][1], af[2][2], af[2][3], ab + 32 * ROWB);
        ldm_x4(b0[0], b1[0], b0[1], b1[1], bb);
#pragma unroll
        for (int mf = 0; mf < 3; ++mf)
#pragma unroll
            for (int nf = 0; nf < 2; ++nf)
                mma_f16(acc[mf][nf], af[mf], b0[nf], b1[nf]);
    }
}

// ---------------- fused dual-cell phase: L0(t) + L1(t-1), 16 chunks --------
__device__ __forceinline__ void cell2_phase(
    uint32_t* sm,
    const uint32_t* __restrict__ Ax, long ldax,   // x(t)
    const uint32_t* __restrict__ H0p,             // h0(t-1)
    const uint32_t* __restrict__ H1p,             // h1(t-2)
    const uint32_t* __restrict__ W0sl,
    const uint32_t* __restrict__ W1sl,
    const float* bS0, const float* bS1,
    float* c0r, float* c1r,
    uint32_t* __restrict__ H0out, uint32_t* __restrict__ H1out,
    int m0, int j0)
{
    const int tid  = threadIdx.x;
    const int arow = tid >> 3, ac4 = tid & 7;
    const int lane = tid & 31, wid = tid >> 5;
    const int wm = wid >> 2, wn = wid & 3;
    const int g4 = lane >> 2, t4 = lane & 3;

    int mrow[3], msz[3];
#pragma unroll
    for (int q = 0; q < 3; ++q) {
        int m = m0 + arow + 32 * q;
        bool p = m < BNR;
        mrow[q] = p ? m : 0;
        msz[q]  = p ? 16 : 0;
    }
    const uint32_t sbase = (uint32_t)__cvta_generic_to_shared(sm);
    uint32_t sb = sbase + (uint32_t)((arow * 36 + ac4 * 4) * 4);
    const uint32_t aPre = sbase +
        (uint32_t)((wm * 48 + (lane & 7) + ((lane >> 3) & 1) * 8) * ROWB +
                   (lane >> 4) * 16);
    const uint32_t bPre = sbase + BOF_B +
        (uint32_t)((wn * 32 + ((lane >> 4) & 1) * 8 + (lane & 7)) * ROWB +
                   ((lane >> 3) & 1) * 16);
    __half* hs0 = (__half*)(sm + HS0_W);
    __half* hs1 = (__half*)(sm + HS1_W);

    auto issue = [&](int c) {
        const int st = c & 3;
        const uint32_t* ap; long lda; int kk;
        if (c < 4)       { ap = Ax;  lda = ldax; kk = c * 32; }
        else if (c < 8)  { ap = H0p; lda = 128;  kk = (c - 4) * 32; }
        else if (c < 12) { ap = H0p; lda = 128;  kk = (c - 8) * 32; }
        else             { ap = H1p; lda = 128;  kk = (c - 12) * 32; }
        const uint32_t* wsl = (c < 8) ? W0sl : W1sl;
        const int kw = (c < 8) ? c * 32 : (c - 8) * 32;
#pragma unroll
        for (int q = 0; q < 3; ++q)
            cpa16(sb + st * STG_B + q * 4608,
                  ap + (long)mrow[q] * lda + kk + ac4 * 4, msz[q]);
#pragma unroll
        for (int q = 0; q < 4; ++q)
            cpa16(sb + st * STG_B + BOF_B + q * 4608,
                  wsl + (long)(arow + 32 * q) * 256 + kw + ac4 * 4, 16);
        CP_COMMIT();
    };

    issue(0); issue(1); issue(2);

    {   // -------- cell 0 (chunks 0..7) --------
        float acc[3][4][4];
#pragma unroll
        for (int a = 0; a < 3; ++a)
#pragma unroll
            for (int b = 0; b < 4; ++b)
#pragma unroll
                for (int k = 0; k < 4; ++k) acc[a][b][k] = 0.f;
        for (int c = 0; c < 8; ++c) {
            asm volatile("cp.async.wait_group 2;");
            __syncthreads();
            issue(c + 3);
            chunk_mma(acc, aPre, bPre, c & 3);
        }
        lstm_epi(acc, bS0, c0r, hs0, wm, wn, g4, t4);
    }
    {   // -------- cell 1 (chunks 8..15) --------
        float acc[3][4][4];
#pragma unroll
        for (int a = 0; a < 3; ++a)
#pragma unroll
            for (int b = 0; b < 4; ++b)
#pragma unroll
                for (int k = 0; k < 4; ++k) acc[a][b][k] = 0.f;
        for (int c = 8; c < 16; ++c) {
            if (c <= 13)      asm volatile("cp.async.wait_group 2;");
            else if (c == 14) asm volatile("cp.async.wait_group 1;");
            else              asm volatile("cp.async.wait_group 0;");
            __syncthreads();
            if (c + 3 < 16) issue(c + 3);
            chunk_mma(acc, aPre, bPre, c & 3);
        }
        lstm_epi(acc, bS1, c1r, hs1, wm, wn, g4, t4);
    }
    __syncthreads();
    if (tid < 192) {   // coalesced stores for both h tiles
        int row = tid >> 1, part = tid & 1;
        int rglob = m0 + row;
        if (rglob < BNR) {
            const uint4* s0 = (const uint4*)(hs0 + row * 40) + part * 2;
            uint4 a0 = s0[0], a1 = s0[1];
            uint4* d0 = (uint4*)(H0out + (long)rglob * 128 + (j0 >> 1)) + part * 2;
            d0[0] = a0; d0[1] = a1;
            const uint4* s1 = (const uint4*)(hs1 + row * 40) + part * 2;
            uint4 b0 = s1[0], b1 = s1[1];
            uint4* d1 = (uint4*)(H1out + (long)rglob * 128 + (j0 >> 1)) + part * 2;
            d1[0] = b0; d1[1] = b1;
        }
    }
    __syncthreads();
}

// ---------------- single LSTM cell phase (edges + decoder L1) --------------
__device__ __forceinline__ void cell_phase(
    uint32_t* sm,
    const uint32_t* __restrict__ A0, long lda0,
    const uint32_t* __restrict__ A1,
    const uint32_t* __restrict__ Wsl,
    const float* biasS, float* cReg,
    uint32_t* __restrict__ Hw,
    int m0, int j0)
{
    const int tid  = threadIdx.x;
    const int arow = tid >> 3, ac4 = tid & 7;
    const int lane = tid & 31, wid = tid >> 5;
    const int wm = wid >> 2, wn = wid & 3;
    const int g4 = lane >> 2, t4 = lane & 3;

    int mrow[3], msz[3];
#pragma unroll
    for (int q = 0; q < 3; ++q) {
        int m = m0 + arow + 32 * q;
        bool p = m < BNR;
        mrow[q] = p ? m : 0;
        msz[q]  = p ? 16 : 0;
    }
    const uint32_t sbase = (uint32_t)__cvta_generic_to_shared(sm);
    uint32_t sb = sbase + (uint32_t)((arow * 36 + ac4 * 4) * 4);
    const uint32_t aPre = sbase +
        (uint32_t)((wm * 48 + (lane & 7) + ((lane >> 3) & 1) * 8) * ROWB +
                   (lane >> 4) * 16);
    const uint32_t bPre = sbase + BOF_B +
        (uint32_t)((wn * 32 + ((lane >> 4) & 1) * 8 + (lane & 7)) * ROWB +
                   ((lane >> 3) & 1) * 16);
    __half* hs0 = (__half*)(sm + HS0_W);

    float acc[3][4][4];
#pragma unroll
    for (int a = 0; a < 3; ++a)
#pragma unroll
        for (int b = 0; b < 4; ++b)
#pragma unroll
            for (int k = 0; k < 4; ++k) acc[a][b][k] = 0.f;

    auto issue = [&](int c) {
        const int st = c & 3;
        const uint32_t* ap; long lda; int kk;
        if (c < 4) { ap = A0; lda = lda0; kk = c * 32; }
        else       { ap = A1; lda = 128;  kk = (c - 4) * 32; }
#pragma unroll
        for (int q = 0; q < 3; ++q)
            cpa16(sb + st * STG_B + q * 4608,
                  ap + (long)mrow[q] * lda + kk + ac4 * 4, msz[q]);
#pragma unroll
        for (int q = 0; q < 4; ++q)
            cpa16(sb + st * STG_B + BOF_B + q * 4608,
                  Wsl + (long)(arow + 32 * q) * 256 + c * 32 + ac4 * 4, 16);
        CP_COMMIT();
    };

    issue(0); issue(1); issue(2);
    for (int c = 0; c < 8; ++c) {
        if (c <= 5)      asm volatile("cp.async.wait_group 2;");
        else if (c == 6) asm volatile("cp.async.wait_group 1;");
        else             asm volatile("cp.async.wait_group 0;");
        __syncthreads();
        if (c + 3 < 8) issue(c + 3);
        chunk_mma(acc, aPre, bPre, c & 3);
    }

    lstm_epi(acc, biasS, cReg, hs0, wm, wn, g4, t4);
    __syncthreads();
    if (tid < 192) {
        int row = tid >> 1, part = tid & 1;
        int rglob = m0 + row;
        if (rglob < BNR) {
            const uint4* src = (const uint4*)(hs0 + row * 40) + part * 2;
            uint4 v0 = src[0], v1 = src[1];
            uint4* dst = (uint4*)(Hw + (long)rglob * 128 + (j0 >> 1)) + part * 2;
            dst[0] = v0; dst[1] = v1;
        }
    }
    __syncthreads();
}

// ---------------- fused decoder phase A: heads1(s) + L0(s), 12 chunks ------
__device__ __forceinline__ void phaseA_fused(
    uint32_t* sm,
    const uint32_t* __restrict__ Ht,              // LN output ht(s)
    const uint32_t* __restrict__ H0p,             // h0 prev
    const uint32_t* __restrict__ Wh1sl,
    const uint32_t* __restrict__ W0sl,
    const float* bSh, const float* bS0,
    float* c0r,
    uint32_t* __restrict__ H0out, float* __restrict__ hid,
    int m0, int j0, int hn0)
{
    const int tid  = threadIdx.x;
    const int arow = tid >> 3, ac4 = tid & 7;
    const int lane = tid & 31, wid = tid >> 5;
    const int wm = wid >> 2, wn = wid & 3;
    const int g4 = lane >> 2, t4 = lane & 3;

    int mrow[3], msz[3];
#pragma unroll
    for (int q = 0; q < 3; ++q) {
        int m = m0 + arow + 32 * q;
        bool p = m < BNR;
        mrow[q] = p ? m : 0;
        msz[q]  = p ? 16 : 0;
    }
    const uint32_t sbase = (uint32_t)__cvta_generic_to_shared(sm);
    uint32_t sb = sbase + (uint32_t)((arow * 36 + ac4 * 4) * 4);
    const uint32_t aPre = sbase +
        (uint32_t)((wm * 48 + (lane & 7) + ((lane >> 3) & 1) * 8) * ROWB +
                   (lane >> 4) * 16);
    const uint32_t bPre32 = sbase + BOF_B +
        (uint32_t)((wn * 32 + ((lane >> 4) & 1) * 8 + (lane & 7)) * ROWB +
                   ((lane >> 3) & 1) * 16);
    const uint32_t bPre16 = sbase + BOF_B +
        (uint32_t)((wn * 16 + ((lane >> 4) & 1) * 8 + (lane & 7)) * ROWB +
                   ((lane >> 3) & 1) * 16);
    __half* hs0 = (__half*)(sm + HS0_W);

    auto issue = [&](int c) {
        const int st = c & 3;
        if (c < 4) {        // heads1: A=ht, B=Wh1 (128w rows, 64 rows)
#pragma unroll
            for (int q = 0; q < 3; ++q)
                cpa16(sb + st * STG_B + q * 4608,
                      Ht + (long)mrow[q] * 128 + c * 32 + ac4 * 4, msz[q]);
#pragma unroll
            for (int q = 0; q < 2; ++q)
                cpa16(sb + st * STG_B + BOF_B + q * 4608,
                      Wh1sl + (long)(arow + 32 * q) * 128 + c * 32 + ac4 * 4, 16);
        } else {            // L0 cell: cc = c-4, A=ht then h0p, B=W0
            const int cc = c - 4;
            const uint32_t* ap = (cc < 4) ? Ht : H0p;
            const int kk = (cc & 3) * 32;
#pragma unroll
            for (int q = 0; q < 3; ++q)
                cpa16(sb + st * STG_B + q * 4608,
                      ap + (long)mrow[q] * 128 + kk + ac4 * 4, msz[q]);
#pragma unroll
            for (int q = 0; q < 4; ++q)
                cpa16(sb + st * STG_B + BOF_B + q * 4608,
                      W0sl + (long)(arow + 32 * q) * 256 + cc * 32 + ac4 * 4, 16);
        }
        CP_COMMIT();
    };

    issue(0); issue(1); issue(2);

    {   // -------- heads1 (chunks 0..3) --------
        float acc[3][2][4];
#pragma unroll
        for (int a = 0; a < 3; ++a)
#pragma unroll
            for (int b = 0; b < 2; ++b)
#pragma unroll
                for (int k = 0; k < 4; ++k) acc[a][b][k] = 0.f;
        for (int c = 0; c < 4; ++c) {
            asm volatile("cp.async.wait_group 2;");
            __syncthreads();
            issue(c + 3);
            chunk_mma_h1(acc, aPre, bPre16, c & 3);
        }
        // heads1 epilogue: writes global only (no smem hazard)
#pragma unroll
        for (int mf = 0; mf < 3; ++mf) {
#pragma unroll
            for (int nf = 0; nf < 2; ++nf) {
                int col = wn * 16 + nf * 8 + 2 * t4;
                int r0 = m0 + wm * 48 + mf * 16 + g4;
                float v0 = acc[mf][nf][0] + bSh[col];
                float v1 = acc[mf][nf][1] + bSh[col + 1];
                float v2 = acc[mf][nf][2] + bSh[col];
                float v3 = acc[mf][nf][3] + bSh[col + 1];
                if (r0 < BNR) {
                    hid[(long)r0 * 512 + hn0 + col]     = fmaxf(v0, 0.f);
                    hid[(long)r0 * 512 + hn0 + col + 1] = fmaxf(v1, 0.f);
                }
                if (r0 + 8 < BNR) {
                    hid[(long)(r0 + 8) * 512 + hn0 + col]     = fmaxf(v2, 0.f);
                    hid[(long)(r0 + 8) * 512 + hn0 + col + 1] = fmaxf(v3, 0.f);
                }
            }
        }
    }
    {   // -------- L0 cell (chunks 4..11) --------
        float acc[3][4][4];
#pragma unroll
        for (int a = 0; a < 3; ++a)
#pragma unroll
            for (int b = 0; b < 4; ++b)
#pragma unroll
                for (int k = 0; k < 4; ++k) acc[a][b][k] = 0.f;
        for (int c = 4; c < 12; ++c) {
            if (c <= 9)       asm volatile("cp.async.wait_group 2;");
            else if (c == 10) asm volatile("cp.async.wait_group 1;");
            else              asm volatile("cp.async.wait_group 0;");
            __syncthreads();
            if (c + 3 < 12) issue(c + 3);
            chunk_mma(acc, aPre, bPre32, c & 3);
        }
        lstm_epi(acc, bS0, c0r, hs0, wm, wn, g4, t4);
    }
    __syncthreads();
    if (tid < 192) {
        int row = tid >> 1, part = tid & 1;
        int rglob = m0 + row;
        if (rglob < BNR) {
            const uint4* src = (const uint4*)(hs0 + row * 40) + part * 2;
            uint4 v0 = src[0], v1 = src[1];
            uint4* dst = (uint4*)(H0out + (long)rglob * 128 + (j0 >> 1)) + part * 2;
            dst[0] = v0; dst[1] = v1;
        }
    }
    __syncthreads();
}

// ---------------- LayerNorm phase (warp per row, 12 rows per CTA) -----------
__device__ __forceinline__ void ln_phase(
    const uint32_t* __restrict__ h1, const float* __restrict__ gam,
    const float* __restrict__ bet, uint32_t* __restrict__ ht, int rowbase)
{
    const int wid = threadIdx.x >> 5, lane = threadIdx.x & 31;
    const unsigned FULL = 0xffffffffu;
#pragma unroll
    for (int rep = 0; rep < 2; ++rep) {
        int rr = rep * 8 + wid;
        int r = rowbase + rr;
        if (rr < 12 && r < BNR) {
            uint4 u = __ldcg((const uint4*)(h1 + (long)r * 128 + lane * 4));
            float v[8];
            __half2 hh;
            hh = *(__half2*)&u.x; v[0] = __low2float(hh); v[1] = __high2float(hh);
            hh = *(__half2*)&u.y; v[2] = __low2float(hh); v[3] = __high2float(hh);
            hh = *(__half2*)&u.z; v[4] = __low2float(hh); v[5] = __high2float(hh);
            hh = *(__half2*)&u.w; v[6] = __low2float(hh); v[7] = __high2float(hh);
            float s1 = 0.f, s2 = 0.f;
#pragma unroll
            for (int i = 0; i < 8; ++i) { s1 += v[i]; s2 += v[i] * v[i]; }
#pragma unroll
            for (int o = 16; o; o >>= 1) {
                s1 += __shfl_xor_sync(FULL, s1, o);
                s2 += __shfl_xor_sync(FULL, s2, o);
            }
            float mean = s1 * (1.f / 256.f);
            float var  = s2 * (1.f / 256.f) - mean * mean;
            float rstd = rsqrtf(var + 1e-5f);
            uint4 o4;
            uint32_t* op = (uint32_t*)&o4;
#pragma unroll
            for (int i = 0; i < 4; ++i) {
                float g0 = __ldg(&gam[lane * 8 + 2 * i]);
                float g1 = __ldg(&gam[lane * 8 + 2 * i + 1]);
                float b0 = __ldg(&bet[lane * 8 + 2 * i]);
                float b1 = __ldg(&bet[lane * 8 + 2 * i + 1]);
                float o0 = (v[2 * i]     - mean) * rstd * g0 + b0;
                float o1 = (v[2 * i + 1] - mean) * rstd * g1 + b1;
                __half2 ho = __floats2half2_rn(o0, o1);
                op[i] = *(uint32_t*)&ho;
            }
            *(uint4*)(ht + (long)r * 128 + lane * 4) = o4;
        }
    }
}

// ---------------- heads layer-2: persistent smem weights --------------------
__device__ __forceinline__ void heads2_phase(
    uint32_t* sm, const float* __restrict__ hid,
    float* __restrict__ out, int s, int rowbase)
{
    float* hs = (float*)sm;            // 12 rows x 512 = 6144 floats (stage0)
    const float* ws = (const float*)(sm + W2S_W);
    const float* bs = ws + 4864;
    const int tid = threadIdx.x;

    for (int i = tid; i < 12 * 128; i += 256) {
        int rr = i >> 7, c4 = i & 127;
        int r = rowbase + rr;
        float4 val = make_float4(0.f, 0.f, 0.f, 0.f);
        if (r < BNR) val = __ldcg((const float4*)(hid + (long)r * 512) + c4);
        ((float4*)hs)[rr * 128 + c4] = val;
    }
    __syncthreads();

    for (int t = tid; t < 12 * 22; t += 256) {
        int row = t / 22, o = t - row * 22;
        int r = rowbase + row;
        if (r < BNR) {
            const float* w; int hbase, klen;
            if (o < 4)      { w = ws + o * 128;             hbase = 0;   klen = 128; }
            else if (o < 6) { w = ws + 512 + (o - 4) * 128; hbase = 128; klen = 128; }
            else            { w = ws + 768 + (o - 6) * 256; hbase = 256; klen = 256; }
            const float* h = hs + row * 512 + hbase;
            float a = 0.f;
            for (int k = 0; k < klen; ++k) a = fmaf(h[k], w[k], a);
            int b = r / 100, n = r - b * 100;
            out[((b * NSTEPS + s) * 100 + n) * 22 + o] = a + bs[o];
        }
    }
    __syncthreads();
}

// ---------------------------------------------------------------------------
__global__ void __launch_bounds__(256, 1)
persist_kernel(const float* __restrict__ lng, const float* __restrict__ lnb,
               const float* __restrict__ cw2, const float* __restrict__ cb2,
               const float* __restrict__ sw2, const float* __restrict__ sb2,
               const float* __restrict__ lw2, const float* __restrict__ lb2,
               float* __restrict__ out)
{
    extern __shared__ uint32_t sm[];
    float* bS0 = (float*)(sm + BIAS_W);
    float* bS1 = bS0 + 128;
    float* bSh = bS1 + 128;
    float* w2s = (float*)(sm + W2S_W);

    const int tid = threadIdx.x;
    const int cta = blockIdx.x;
    const int mx = cta % MT, ny = cta / MT;
    const int m0  = mx * MROWS;
    const int nb0 = ny * 128;           // gate-row base
    const int j0  = ny * 32;            // j-col base
    const int hn0 = ny * 64;            // heads1 col base
    const int rowbase = m0 + ny * 12;   // LN/heads2 group-local rows (12 each)

    if (tid < 128) { bS0[tid] = g_bre0[nb0 + tid]; bS1[tid] = g_bre1[nb0 + tid]; }
    if (tid < 64)  { bSh[tid] = g_bh1[hn0 + tid]; }
    // persistent layer-2 weights + biases (loaded once)
    for (int i = tid; i < 128; i += 256)
        ((float4*)w2s)[i] = __ldg((const float4*)cw2 + i);
    for (int i = tid; i < 64; i += 256)
        ((float4*)(w2s + 512))[i] = __ldg((const float4*)sw2 + i);
    for (int i = tid; i < 1024; i += 256)
        ((float4*)(w2s + 768))[i] = __ldg((const float4*)lw2 + i);
    if (tid < 22) {
        float b;
        if (tid < 4)      b = __ldg(&cb2[tid]);
        else if (tid < 6) b = __ldg(&sb2[tid - 4]);
        else              b = __ldg(&lb2[tid - 6]);
        w2s[4864 + tid] = b;
    }
    __syncthreads();

    float c0r[12], c1r[12];
#pragma unroll
    for (int i = 0; i < 12; ++i) { c0r[i] = 0.f; c1r[i] = 0.f; }

    const uint32_t* W0sl  = g_Wre0 + (long)nb0 * 256;
    const uint32_t* W1sl  = g_Wre1 + (long)nb0 * 256;
    const uint32_t* Wh1sl = g_Wh1 + (long)hn0 * 128;

    // ---------------- encoder (fused: phase t = L0(t)+L1(t-1)) --------------
    cell_phase(sm, g_xw, (long)SEQ * 128, g_h0buf[0],
               W0sl, bS0, c0r, g_h0buf[1], m0, j0);            // L0(0)
    gbar_ns(mx);
    for (int t = 1; t < SEQ; ++t) {
        cell2_phase(sm, g_xw + (long)t * 128, (long)SEQ * 128,
                    g_h0buf[t & 1], g_h1buf[(t + 1) & 1],
                    W0sl, W1sl, bS0, bS1, c0r, c1r,
                    g_h0buf[(t + 1) & 1], g_h1buf[t & 1], m0, j0);
        gbar_ns(mx);
    }
    cell_phase(sm, g_h0buf[0], 128, g_h1buf[1],
               W1sl, bS1, c1r, g_h1buf[0], m0, j0);             // L1(63)
    gbar_ns(mx);
    ln_phase(g_h1buf[0], lng, lnb, g_htw, rowbase);
    gbar(mx);

    // ---------------- decoder ----------------
    for (int s = 0; s < NSTEPS; ++s) {
        phaseA_fused(sm, g_htw, g_h0buf[s & 1], Wh1sl, W0sl, bSh, bS0,
                     c0r, g_h0buf[(s + 1) & 1], g_hid, m0, j0, hn0);
        gbar_ns(mx);
        cell_phase(sm, g_h0buf[(s + 1) & 1], 128, g_h1buf[s & 1],
                   W1sl, bS1, c1r, g_h1buf[(s + 1) & 1], m0, j0);
        heads2_phase(sm, g_hid, out, s, rowbase);
        if (s < NSTEPS - 1) {
            gbar_ns(mx);
            ln_phase(g_h1buf[(s + 1) & 1], lng, lnb, g_htw, rowbase);
            gbar(mx);
        }
    }
}

// ---------------------------------------------------------------------------
extern "C" void kernel_launch(void* const* d_in, const int* in_sizes, int n_in,
                              void* d_out, int out_size)
{
    (void)in_sizes; (void)n_in; (void)out_size;
    const float* x    = (const float*)d_in[0];
    const float* Wih0 = (const float*)d_in[1];
    const float* Whh0 = (const float*)d_in[2];
    const float* bih0 = (const float*)d_in[3];
    const float* bhh0 = (const float*)d_in[4];
    const float* Wih1 = (const float*)d_in[5];
    const float* Whh1 = (const float*)d_in[6];
    const float* bih1 = (const float*)d_in[7];
    const float* bhh1 = (const float*)d_in[8];
    const float* lng  = (const float*)d_in[9];
    const float* lnb  = (const float*)d_in[10];
    const float* cw1  = (const float*)d_in[11];
    const float* cb1  = (const float*)d_in[12];
    const float* cw2  = (const float*)d_in[13];
    const float* cb2  = (const float*)d_in[14];
    const float* sw1  = (const float*)d_in[15];
    const float* sb1  = (const float*)d_in[16];
    const float* sw2  = (const float*)d_in[17];
    const float* sb2  = (const float*)d_in[18];
    const float* lw1  = (const float*)d_in[19];
    const float* lb1  = (const float*)d_in[20];
    const float* lw2  = (const float*)d_in[21];
    const float* lb2  = (const float*)d_in[22];
    float* out = (float*)d_out;

    uint32_t *Wre0, *Wre1;
    float *bre0, *bre1;
    cudaGetSymbolAddress((void**)&Wre0, g_Wre0);
    cudaGetSymbolAddress((void**)&Wre1, g_Wre1);
    cudaGetSymbolAddress((void**)&bre0, g_bre0);
    cudaGetSymbolAddress((void**)&bre1, g_bre1);

    cudaFuncSetAttribute(persist_kernel,
                         cudaFuncAttributeMaxDynamicSharedMemorySize, PSMEM);

    transpose_kernel<<<(BNR * SEQ * 32 + 255) / 256, 256>>>(x);
    rearr_w_kernel<<<1024, 256>>>(Wih0, Whh0, bih0, bhh0, Wre0, bre0);
    rearr_w_kernel<<<1024, 256>>>(Wih1, Whh1, bih1, bhh1, Wre1, bre1);
    rearr_h1_kernel<<<256, 256>>>(cw1, cb1, sw1, sb1, lw1, lb1);
    zero_state_kernel<<<800, 256>>>();

    persist_kernel<<<NCTA, 256, PSMEM>>>(lng, lnb, cw2, cb2, sw2, sb2,
                                         lw2, lb2, out);
}

// round 17
// speedup vs baseline: 1.0533x; 1.0533x over previous
#include <cuda_runtime.h>
#include <cuda_fp16.h>
#include <cstdint>

#define BNR    1600
#define HD     256
#define SEQ    64
#define NSTEPS 10
#define MT     17          /* M groups of 96 rows */
#define MROWS  96
#define NCTA   (MT * 8)    /* 136 CTAs, one wave on 148 SMs */

// ------------------------- static device scratch --------------------------
__device__ uint32_t g_xw  [BNR * SEQ * 128];    // x fp16 [m][t][128w]
__device__ uint32_t g_h0buf[2][BNR * 128];
__device__ uint32_t g_h1buf[2][BNR * 128];
__device__ uint32_t g_htw [BNR * 128];          // LN output fp16
__device__ float    g_hid [BNR * 512];
__device__ uint32_t g_Wre0[1024 * 256];         // fp16, rows (j*4+g), k=[Wih|Whh]
__device__ uint32_t g_Wre1[1024 * 256];
__device__ float    g_bre0[1024];
__device__ float    g_bre1[1024];
__device__ uint32_t g_Wh1 [512 * 128];          // heads layer1 weights fp16
__device__ float    g_bh1 [512];
__device__ unsigned g_grpCnt[MT * 32];          // per-group barrier (128B stride)
__device__ unsigned g_grpGen[MT * 32];

// ------------------------------ helpers -----------------------------------
__device__ __forceinline__ void mma_f16(float* d, const uint32_t* a,
                                        uint32_t b0, uint32_t b1) {
    asm volatile(
        "mma.sync.aligned.m16n8k16.row.col.f32.f16.f16.f32 "
        "{%0,%1,%2,%3}, {%4,%5,%6,%7}, {%8,%9}, {%0,%1,%2,%3};"
        : "+f"(d[0]), "+f"(d[1]), "+f"(d[2]), "+f"(d[3])
        : "r"(a[0]), "r"(a[1]), "r"(a[2]), "r"(a[3]), "r"(b0), "r"(b1));
}
__device__ __forceinline__ void ldm_x4(uint32_t& r0, uint32_t& r1,
                                       uint32_t& r2, uint32_t& r3,
                                       uint32_t addr) {
    asm volatile("ldmatrix.sync.aligned.m8n8.x4.shared.b16 {%0,%1,%2,%3}, [%4];"
                 : "=r"(r0), "=r"(r1), "=r"(r2), "=r"(r3) : "r"(addr));
}
__device__ __forceinline__ float tanha(float x) {
    float r;
    asm("tanh.approx.f32 %0, %1;" : "=f"(r) : "f"(x));
    return r;
}
__device__ __forceinline__ float sigf(float x) {
    return fmaf(tanha(0.5f * x), 0.5f, 0.5f);
}
__device__ __forceinline__ void cpa16(uint32_t saddr, const void* g, int sz) {
    asm volatile("cp.async.cg.shared.global [%0], [%1], 16, %2;"
                 :: "r"(saddr), "l"(g), "r"(sz));
}
#define CP_COMMIT() asm volatile("cp.async.commit_group;")

// per-group barrier
__device__ __forceinline__ void gbar_body(int grp) {
    if (threadIdx.x == 0) {
        __threadfence();
        unsigned* cnt = &g_grpCnt[grp * 32];
        unsigned* gen = &g_grpGen[grp * 32];
        unsigned g = *(volatile unsigned*)gen;
        if (atomicAdd(cnt, 1u) == 7u) {
            *(volatile unsigned*)cnt = 0u;
            __threadfence();
            atomicExch(gen, g + 1);
        } else {
            while (*(volatile unsigned*)gen == g) { }
        }
        __threadfence();
    }
    __syncthreads();
}
__device__ __forceinline__ void gbar(int grp)    { __syncthreads(); gbar_body(grp); }
__device__ __forceinline__ void gbar_ns(int grp) { gbar_body(grp); }

// ------------------------------ setup kernels -----------------------------
__global__ void transpose_kernel(const float* __restrict__ x) {
    int id = blockIdx.x * blockDim.x + threadIdx.x;
    if (id >= BNR * SEQ * 32) return;
    int w8 = id & 31;
    int t  = (id >> 5) & 63;
    int m  = id >> 11;
    int b  = m / 100;
    int n  = m - b * 100;
    const float4* src = (const float4*)x + ((((long)(b * SEQ + t) * 100 + n) * 64) + 2 * w8);
    float4 v0 = src[0], v1 = src[1];
    __half2 h0 = __floats2half2_rn(v0.x, v0.y);
    __half2 h1 = __floats2half2_rn(v0.z, v0.w);
    __half2 h2 = __floats2half2_rn(v1.x, v1.y);
    __half2 h3 = __floats2half2_rn(v1.z, v1.w);
    uint4 o;
    o.x = *(uint32_t*)&h0; o.y = *(uint32_t*)&h1;
    o.z = *(uint32_t*)&h2; o.w = *(uint32_t*)&h3;
    ((uint4*)g_xw)[((long)m * SEQ + t) * 32 + w8] = o;
}

__global__ void rearr_w_kernel(const float* __restrict__ Wih,
                               const float* __restrict__ Whh,
                               const float* __restrict__ bih,
                               const float* __restrict__ bhh,
                               uint32_t* __restrict__ Wre,
                               float* __restrict__ bre) {
    int id = blockIdx.x * 256 + threadIdx.x;
    if (id >= 1024 * 256) return;
    int nre = id >> 8, kw = id & 255;
    int j = nre >> 2, g = nre & 3;
    int srow = g * 256 + j;
    int k = kw * 2;
    float v0, v1;
    if (k < 256) { v0 = Wih[srow * 256 + k];       v1 = Wih[srow * 256 + k + 1]; }
    else         { v0 = Whh[srow * 256 + k - 256]; v1 = Whh[srow * 256 + k - 255]; }
    __half2 h = __floats2half2_rn(v0, v1);
    Wre[id] = *(uint32_t*)&h;
    if (kw == 0) bre[nre] = bih[srow] + bhh[srow];
}

__global__ void rearr_h1_kernel(const float* __restrict__ cw1, const float* __restrict__ cb1,
                                const float* __restrict__ sw1, const float* __restrict__ sb1,
                                const float* __restrict__ lw1, const float* __restrict__ lb1) {
    int id = blockIdx.x * 256 + threadIdx.x;
    if (id >= 512 * 128) return;
    int row = id >> 7, kw = id & 127;
    int k = kw * 2;
    const float* w; float b;
    if (row < 128)      { w = cw1 + row * 256;         b = cb1[row]; }
    else if (row < 256) { w = sw1 + (row - 128) * 256; b = sb1[row - 128]; }
    else                { w = lw1 + (row - 256) * 256; b = lb1[row - 256]; }
    __half2 h = __floats2half2_rn(w[k], w[k + 1]);
    g_Wh1[id] = *(uint32_t*)&h;
    if (kw == 0) g_bh1[row] = b;
}

__global__ void zero_state_kernel() {
    int id = blockIdx.x * blockDim.x + threadIdx.x;
    if (id < BNR * 128) { g_h0buf[0][id] = 0u; g_h1buf[0][id] = 0u; }
    if (id < MT * 32) { g_grpCnt[id] = 0u; g_grpGen[id] = 0u; }
}

// ---------------------------------------------------------------------------
// smem: 3 stages x (A 96x68w + B 128x68w) + biases + 2 h-stages + W2 cache
// 68-word rows (272B): 272 mod 128 = 16 -> same conflict-free ldmatrix phase
#define STG_W   15232                 /* (96+128)*68 words per stage */
#define STG_B   (STG_W * 4)
#define BOF_B   (96 * 68 * 4)         /* 26112: B offset within stage */
#define BIAS_W  (3 * STG_W)           /* 45696 */
#define HS0_W   (BIAS_W + 320)
#define HS1_W   (HS0_W + 1920)
#define W2S_W   (HS1_W + 1920)
#define PSMEM   ((W2S_W + 4896) * 4)  /* ~214 KB */
#define ROWB    272                   /* 68 words * 4 bytes */

// ---------------- shared epilogue helper (per-warp, writes hs) -------------
__device__ __forceinline__ void lstm_epi(
    const float acc[3][4][4], const float* biasS, float* cReg, __half* hs,
    int wm, int wn, int g4, int t4)
{
    const bool oddl = (t4 & 1);
    const unsigned FULL = 0xffffffffu;
#pragma unroll
    for (int mf = 0; mf < 3; ++mf) {
#pragma unroll
        for (int nf = 0; nf < 4; ++nf) {
            float c0v = acc[mf][nf][0], c1v = acc[mf][nf][1];
            float c2v = acc[mf][nf][2], c3v = acc[mf][nf][3];
            float x0 = __shfl_xor_sync(FULL, c0v, 1);
            float x1 = __shfl_xor_sync(FULL, c1v, 1);
            float x2 = __shfl_xor_sync(FULL, c2v, 1);
            float x3 = __shfl_xor_sync(FULL, c3v, 1);
            float gi, gf, gg, go; int rloc;
            if (!oddl) { gi = c0v; gf = c1v; gg = x0;  go = x1;  rloc = g4; }
            else       { gi = x2;  gf = x3;  gg = c2v; go = c3v; rloc = g4 + 8; }
            int rowloc = wm * 48 + mf * 16 + rloc;       // 0..95
            int jl = wn * 8 + nf * 2 + (t4 >> 1);        // 0..31
            gi += biasS[jl * 4 + 0];
            gf += biasS[jl * 4 + 1];
            gg += biasS[jl * 4 + 2];
            go += biasS[jl * 4 + 3];
            float cold = cReg[mf * 4 + nf];
            float cn = sigf(gf) * cold + sigf(gi) * tanha(gg);
            float hn = sigf(go) * tanha(cn);
            cReg[mf * 4 + nf] = cn;
            hs[rowloc * 40 + jl] = __float2half_rn(hn);
        }
    }
}

// ---------------- compute one 64-word K-chunk (cell: 4 nf) ------------------
__device__ __forceinline__ void chunk_mma(
    float acc[3][4][4], uint32_t aPre, uint32_t bPre, int st)
{
#pragma unroll
    for (int ks = 0; ks < 64; ks += 8) {
        uint32_t af[3][4], b0[4], b1[4];
        uint32_t ab = aPre + st * STG_B + ks * 4;
        uint32_t bb = bPre + st * STG_B + ks * 4;
        ldm_x4(af[0][0], af[0][1], af[0][2], af[0][3], ab);
        ldm_x4(af[1][0], af[1][1], af[1][2], af[1][3], ab + 16 * ROWB);
        ldm_x4(af[2][0], af[2][1], af[2][2], af[2][3], ab + 32 * ROWB);
        ldm_x4(b0[0], b1[0], b0[1], b1[1], bb);
        ldm_x4(b0[2], b1[2], b0[3], b1[3], bb + 16 * ROWB);
#pragma unroll
        for (int mf = 0; mf < 3; ++mf)
#pragma unroll
            for (int nf = 0; nf < 4; ++nf)
                mma_f16(acc[mf][nf], af[mf], b0[nf], b1[nf]);
    }
}

// ---------------- compute one 64-word K-chunk (heads1: 2 nf) ----------------
__device__ __forceinline__ void chunk_mma_h1(
    float acc[3][2][4], uint32_t aPre, uint32_t bPre, int st)
{
#pragma unroll
    for (int ks = 0; ks < 64; ks += 8) {
        uint32_t af[3][4], b0[2], b1[2];
        uint32_t ab = aPre + st * STG_B + ks * 4;
        uint32_t bb = bPre + st * STG_B + ks * 4;
        ldm_x4(af[0][0], af[0][1], af[0][2], af[0][3], ab);
        ldm_x4(af[1][0], af[1][1], af[1][2], af[1][3], ab + 16 * ROWB);
        ldm_x4(af[2][0], af[2][1], af[2][2], af[2][3], ab + 32 * ROWB);
        ldm_x4(b0[0], b1[0], b0[1], b1[1], bb);
#pragma unroll
        for (int mf = 0; mf < 3; ++mf)
#pragma unroll
            for (int nf = 0; nf < 2; ++nf)
                mma_f16(acc[mf][nf], af[mf], b0[nf], b1[nf]);
    }
}

// ---------------- fused dual-cell phase: L0(t) + L1(t-1), 8 chunks ---------
__device__ __forceinline__ void cell2_phase(
    uint32_t* sm,
    const uint32_t* __restrict__ Ax, long ldax,   // x(t)
    const uint32_t* __restrict__ H0p,             // h0(t-1)
    const uint32_t* __restrict__ H1p,             // h1(t-2)
    const uint32_t* __restrict__ W0sl,
    const uint32_t* __restrict__ W1sl,
    const float* bS0, const float* bS1,
    float* c0r, float* c1r,
    uint32_t* __restrict__ H0out, uint32_t* __restrict__ H1out,
    int m0, int j0)
{
    const int tid  = threadIdx.x;
    const int arow = tid >> 3, ac4 = tid & 7;
    const int lane = tid & 31, wid = tid >> 5;
    const int wm = wid >> 2, wn = wid & 3;
    const int g4 = lane >> 2, t4 = lane & 3;

    int mrow[3], msz[3];
#pragma unroll
    for (int q = 0; q < 3; ++q) {
        int m = m0 + arow + 32 * q;
        bool p = m < BNR;
        mrow[q] = p ? m : 0;
        msz[q]  = p ? 16 : 0;
    }
    const uint32_t sbase = (uint32_t)__cvta_generic_to_shared(sm);
    uint32_t sb = sbase + (uint32_t)((arow * 68 + ac4 * 4) * 4);
    const uint32_t aPre = sbase +
        (uint32_t)((wm * 48 + (lane & 7) + ((lane >> 3) & 1) * 8) * ROWB +
                   (lane >> 4) * 16);
    const uint32_t bPre = sbase + BOF_B +
        (uint32_t)((wn * 32 + ((lane >> 4) & 1) * 8 + (lane & 7)) * ROWB +
                   ((lane >> 3) & 1) * 16);
    __half* hs0 = (__half*)(sm + HS0_W);
    __half* hs1 = (__half*)(sm + HS1_W);

    auto issue = [&](int c) {
        const int st = c % 3;
        const uint32_t* ap; long lda; int kk;
        if (c < 2)      { ap = Ax;  lda = ldax; kk = c * 64; }
        else if (c < 4) { ap = H0p; lda = 128;  kk = (c - 2) * 64; }
        else if (c < 6) { ap = H0p; lda = 128;  kk = (c - 4) * 64; }
        else            { ap = H1p; lda = 128;  kk = (c - 6) * 64; }
        const uint32_t* wsl = (c < 4) ? W0sl : W1sl;
        const int kw = (c < 4) ? c * 64 : (c - 4) * 64;
#pragma unroll
        for (int q = 0; q < 3; ++q)
#pragma unroll
            for (int h = 0; h < 2; ++h)
                cpa16(sb + st * STG_B + q * 8704 + h * 128,
                      ap + (long)mrow[q] * lda + kk + h * 32 + ac4 * 4, msz[q]);
#pragma unroll
        for (int q = 0; q < 4; ++q)
#pragma unroll
            for (int h = 0; h < 2; ++h)
                cpa16(sb + st * STG_B + BOF_B + q * 8704 + h * 128,
                      wsl + (long)(arow + 32 * q) * 256 + kw + h * 32 + ac4 * 4, 16);
        CP_COMMIT();
    };

    issue(0); issue(1);

    {   // -------- cell 0 (chunks 0..3) --------
        float acc[3][4][4];
#pragma unroll
        for (int a = 0; a < 3; ++a)
#pragma unroll
            for (int b = 0; b < 4; ++b)
#pragma unroll
                for (int k = 0; k < 4; ++k) acc[a][b][k] = 0.f;
        for (int c = 0; c < 4; ++c) {
            asm volatile("cp.async.wait_group 1;");
            __syncthreads();
            issue(c + 2);
            chunk_mma(acc, aPre, bPre, c % 3);
        }
        lstm_epi(acc, bS0, c0r, hs0, wm, wn, g4, t4);
    }
    {   // -------- cell 1 (chunks 4..7) --------
        float acc[3][4][4];
#pragma unroll
        for (int a = 0; a < 3; ++a)
#pragma unroll
            for (int b = 0; b < 4; ++b)
#pragma unroll
                for (int k = 0; k < 4; ++k) acc[a][b][k] = 0.f;
        for (int c = 4; c < 8; ++c) {
            if (c < 7) asm volatile("cp.async.wait_group 1;");
            else       asm volatile("cp.async.wait_group 0;");
            __syncthreads();
            if (c + 2 < 8) issue(c + 2);
            chunk_mma(acc, aPre, bPre, c % 3);
        }
        lstm_epi(acc, bS1, c1r, hs1, wm, wn, g4, t4);
    }
    __syncthreads();
    if (tid < 192) {   // coalesced stores for both h tiles
        int row = tid >> 1, part = tid & 1;
        int rglob = m0 + row;
        if (rglob < BNR) {
            const uint4* s0 = (const uint4*)(hs0 + row * 40) + part * 2;
            uint4 a0 = s0[0], a1 = s0[1];
            uint4* d0 = (uint4*)(H0out + (long)rglob * 128 + (j0 >> 1)) + part * 2;
            d0[0] = a0; d0[1] = a1;
            const uint4* s1 = (const uint4*)(hs1 + row * 40) + part * 2;
            uint4 b0 = s1[0], b1 = s1[1];
            uint4* d1 = (uint4*)(H1out + (long)rglob * 128 + (j0 >> 1)) + part * 2;
            d1[0] = b0; d1[1] = b1;
        }
    }
    __syncthreads();
}

// ---------------- single LSTM cell phase (edges + decoder L1), 4 chunks ----
__device__ __forceinline__ void cell_phase(
    uint32_t* sm,
    const uint32_t* __restrict__ A0, long lda0,
    const uint32_t* __restrict__ A1,
    const uint32_t* __restrict__ Wsl,
    const float* biasS, float* cReg,
    uint32_t* __restrict__ Hw,
    int m0, int j0)
{
    const int tid  = threadIdx.x;
    const int arow = tid >> 3, ac4 = tid & 7;
    const int lane = tid & 31, wid = tid >> 5;
    const int wm = wid >> 2, wn = wid & 3;
    const int g4 = lane >> 2, t4 = lane & 3;

    int mrow[3], msz[3];
#pragma unroll
    for (int q = 0; q < 3; ++q) {
        int m = m0 + arow + 32 * q;
        bool p = m < BNR;
        mrow[q] = p ? m : 0;
        msz[q]  = p ? 16 : 0;
    }
    const uint32_t sbase = (uint32_t)__cvta_generic_to_shared(sm);
    uint32_t sb = sbase + (uint32_t)((arow * 68 + ac4 * 4) * 4);
    const uint32_t aPre = sbase +
        (uint32_t)((wm * 48 + (lane & 7) + ((lane >> 3) & 1) * 8) * ROWB +
                   (lane >> 4) * 16);
    const uint32_t bPre = sbase + BOF_B +
        (uint32_t)((wn * 32 + ((lane >> 4) & 1) * 8 + (lane & 7)) * ROWB +
                   ((lane >> 3) & 1) * 16);
    __half* hs0 = (__half*)(sm + HS0_W);

    float acc[3][4][4];
#pragma unroll
    for (int a = 0; a < 3; ++a)
#pragma unroll
        for (int b = 0; b < 4; ++b)
#pragma unroll
            for (int k = 0; k < 4; ++k) acc[a][b][k] = 0.f;

    auto issue = [&](int c) {
        const int st = c % 3;
        const uint32_t* ap; long lda; int kk;
        if (c < 2) { ap = A0; lda = lda0; kk = c * 64; }
        else       { ap = A1; lda = 128;  kk = (c - 2) * 64; }
#pragma unroll
        for (int q = 0; q < 3; ++q)
#pragma unroll
            for (int h = 0; h < 2; ++h)
                cpa16(sb + st * STG_B + q * 8704 + h * 128,
                      ap + (long)mrow[q] * lda + kk + h * 32 + ac4 * 4, msz[q]);
#pragma unroll
        for (int q = 0; q < 4; ++q)
#pragma unroll
            for (int h = 0; h < 2; ++h)
                cpa16(sb + st * STG_B + BOF_B + q * 8704 + h * 128,
                      Wsl + (long)(arow + 32 * q) * 256 + c * 64 + h * 32 + ac4 * 4, 16);
        CP_COMMIT();
    };

    issue(0); issue(1);
    for (int c = 0; c < 4; ++c) {
        if (c < 3) asm volatile("cp.async.wait_group 1;");
        else       asm volatile("cp.async.wait_group 0;");
        __syncthreads();
        if (c + 2 < 4) issue(c + 2);
        chunk_mma(acc, aPre, bPre, c % 3);
    }

    lstm_epi(acc, biasS, cReg, hs0, wm, wn, g4, t4);
    __syncthreads();
    if (tid < 192) {
        int row = tid >> 1, part = tid & 1;
        int rglob = m0 + row;
        if (rglob < BNR) {
            const uint4* src = (const uint4*)(hs0 + row * 40) + part * 2;
            uint4 v0 = src[0], v1 = src[1];
            uint4* dst = (uint4*)(Hw + (long)rglob * 128 + (j0 >> 1)) + part * 2;
            dst[0] = v0; dst[1] = v1;
        }
    }
    __syncthreads();
}

// ---------------- fused decoder phase A: heads1(s) + L0(s), 6 chunks -------
__device__ __forceinline__ void phaseA_fused(
    uint32_t* sm,
    const uint32_t* __restrict__ Ht,              // LN output ht(s)
    const uint32_t* __restrict__ H0p,             // h0 prev
    const uint32_t* __restrict__ Wh1sl,
    const uint32_t* __restrict__ W0sl,
    const float* bSh, const float* bS0,
    float* c0r,
    uint32_t* __restrict__ H0out, float* __restrict__ hid,
    int m0, int j0, int hn0)
{
    const int tid  = threadIdx.x;
    const int arow = tid >> 3, ac4 = tid & 7;
    const int lane = tid & 31, wid = tid >> 5;
    const int wm = wid >> 2, wn = wid & 3;
    const int g4 = lane >> 2, t4 = lane & 3;

    int mrow[3], msz[3];
#pragma unroll
    for (int q = 0; q < 3; ++q) {
        int m = m0 + arow + 32 * q;
        bool p = m < BNR;
        mrow[q] = p ? m : 0;
        msz[q]  = p ? 16 : 0;
    }
    const uint32_t sbase = (uint32_t)__cvta_generic_to_shared(sm);
    uint32_t sb = sbase + (uint32_t)((arow * 68 + ac4 * 4) * 4);
    const uint32_t aPre = sbase +
        (uint32_t)((wm * 48 + (lane & 7) + ((lane >> 3) & 1) * 8) * ROWB +
                   (lane >> 4) * 16);
    const uint32_t bPre32 = sbase + BOF_B +
        (uint32_t)((wn * 32 + ((lane >> 4) & 1) * 8 + (lane & 7)) * ROWB +
                   ((lane >> 3) & 1) * 16);
    const uint32_t bPre16 = sbase + BOF_B +
        (uint32_t)((wn * 16 + ((lane >> 4) & 1) * 8 + (lane & 7)) * ROWB +
                   ((lane >> 3) & 1) * 16);
    __half* hs0 = (__half*)(sm + HS0_W);

    auto issue = [&](int c) {
        const int st = c % 3;
        if (c < 2) {        // heads1: A=ht, B=Wh1 (128w rows, 64 rows)
#pragma unroll
            for (int q = 0; q < 3; ++q)
#pragma unroll
                for (int h = 0; h < 2; ++h)
                    cpa16(sb + st * STG_B + q * 8704 + h * 128,
                          Ht + (long)mrow[q] * 128 + c * 64 + h * 32 + ac4 * 4,
                          msz[q]);
#pragma unroll
            for (int q = 0; q < 2; ++q)
#pragma unroll
                for (int h = 0; h < 2; ++h)
                    cpa16(sb + st * STG_B + BOF_B + q * 8704 + h * 128,
                          Wh1sl + (long)(arow + 32 * q) * 128 + c * 64 + h * 32 + ac4 * 4, 16);
        } else {            // L0 cell: cc = c-2, A=ht then h0p, B=W0
            const int cc = c - 2;
            const uint32_t* ap = (cc < 2) ? Ht : H0p;
            const int kk = (cc & 1) * 64;
#pragma unroll
            for (int q = 0; q < 3; ++q)
#pragma unroll
                for (int h = 0; h < 2; ++h)
                    cpa16(sb + st * STG_B + q * 8704 + h * 128,
                          ap + (long)mrow[q] * 128 + kk + h * 32 + ac4 * 4, msz[q]);
#pragma unroll
            for (int q = 0; q < 4; ++q)
#pragma unroll
                for (int h = 0; h < 2; ++h)
                    cpa16(sb + st * STG_B + BOF_B + q * 8704 + h * 128,
                          W0sl + (long)(arow + 32 * q) * 256 + cc * 64 + h * 32 + ac4 * 4, 16);
        }
        CP_COMMIT();
    };

    issue(0); issue(1);

    {   // -------- heads1 (chunks 0..1) --------
        float acc[3][2][4];
#pragma unroll
        for (int a = 0; a < 3; ++a)
#pragma unroll
            for (int b = 0; b < 2; ++b)
#pragma unroll
                for (int k = 0; k < 4; ++k) acc[a][b][k] = 0.f;
        for (int c = 0; c < 2; ++c) {
            asm volatile("cp.async.wait_group 1;");
            __syncthreads();
            issue(c + 2);
            chunk_mma_h1(acc, aPre, bPre16, c % 3);
        }
        // heads1 epilogue: writes global only (no smem hazard)
#pragma unroll
        for (int mf = 0; mf < 3; ++mf) {
#pragma unroll
            for (int nf = 0; nf < 2; ++nf) {
                int col = wn * 16 + nf * 8 + 2 * t4;
                int r0 = m0 + wm * 48 + mf * 16 + g4;
                float v0 = acc[mf][nf][0] + bSh[col];
                float v1 = acc[mf][nf][1] + bSh[col + 1];
                float v2 = acc[mf][nf][2] + bSh[col];
                float v3 = acc[mf][nf][3] + bSh[col + 1];
                if (r0 < BNR) {
                    hid[(long)r0 * 512 + hn0 + col]     = fmaxf(v0, 0.f);
                    hid[(long)r0 * 512 + hn0 + col + 1] = fmaxf(v1, 0.f);
                }
                if (r0 + 8 < BNR) {
                    hid[(long)(r0 + 8) * 512 + hn0 + col]     = fmaxf(v2, 0.f);
                    hid[(long)(r0 + 8) * 512 + hn0 + col + 1] = fmaxf(v3, 0.f);
                }
            }
        }
    }
    {   // -------- L0 cell (chunks 2..5) --------
        float acc[3][4][4];
#pragma unroll
        for (int a = 0; a < 3; ++a)
#pragma unroll
            for (int b = 0; b < 4; ++b)
#pragma unroll
                for (int k = 0; k < 4; ++k) acc[a][b][k] = 0.f;
        for (int c = 2; c < 6; ++c) {
            if (c < 5) asm volatile("cp.async.wait_group 1;");
            else       asm volatile("cp.async.wait_group 0;");
            __syncthreads();
            if (c + 2 < 6) issue(c + 2);
            chunk_mma(acc, aPre, bPre32, c % 3);
        }
        lstm_epi(acc, bS0, c0r, hs0, wm, wn, g4, t4);
    }
    __syncthreads();
    if (tid < 192) {
        int row = tid >> 1, part = tid & 1;
        int rglob = m0 + row;
        if (rglob < BNR) {
            const uint4* src = (const uint4*)(hs0 + row * 40) + part * 2;
            uint4 v0 = src[0], v1 = src[1];
            uint4* dst = (uint4*)(H0out + (long)rglob * 128 + (j0 >> 1)) + part * 2;
            dst[0] = v0; dst[1] = v1;
        }
    }
    __syncthreads();
}

// ---------------- LayerNorm phase (warp per row, 12 rows per CTA) -----------
__device__ __forceinline__ void ln_phase(
    const uint32_t* __restrict__ h1, const float* __restrict__ gam,
    const float* __restrict__ bet, uint32_t* __restrict__ ht, int rowbase)
{
    const int wid = threadIdx.x >> 5, lane = threadIdx.x & 31;
    const unsigned FULL = 0xffffffffu;
#pragma unroll
    for (int rep = 0; rep < 2; ++rep) {
        int rr = rep * 8 + wid;
        int r = rowbase + rr;
        if (rr < 12 && r < BNR) {
            uint4 u = __ldcg((const uint4*)(h1 + (long)r * 128 + lane * 4));
            float v[8];
            __half2 hh;
            hh = *(__half2*)&u.x; v[0] = __low2float(hh); v[1] = __high2float(hh);
            hh = *(__half2*)&u.y; v[2] = __low2float(hh); v[3] = __high2float(hh);
            hh = *(__half2*)&u.z; v[4] = __low2float(hh); v[5] = __high2float(hh);
            hh = *(__half2*)&u.w; v[6] = __low2float(hh); v[7] = __high2float(hh);
            float s1 = 0.f, s2 = 0.f;
#pragma unroll
            for (int i = 0; i < 8; ++i) { s1 += v[i]; s2 += v[i] * v[i]; }
#pragma unroll
            for (int o = 16; o; o >>= 1) {
                s1 += __shfl_xor_sync(FULL, s1, o);
                s2 += __shfl_xor_sync(FULL, s2, o);
            }
            float mean = s1 * (1.f / 256.f);
            float var  = s2 * (1.f / 256.f) - mean * mean;
            float rstd = rsqrtf(var + 1e-5f);
            uint4 o4;
            uint32_t* op = (uint32_t*)&o4;
#pragma unroll
            for (int i = 0; i < 4; ++i) {
                float g0 = __ldg(&gam[lane * 8 + 2 * i]);
                float g1 = __ldg(&gam[lane * 8 + 2 * i + 1]);
                float b0 = __ldg(&bet[lane * 8 + 2 * i]);
                float b1 = __ldg(&bet[lane * 8 + 2 * i + 1]);
                float o0 = (v[2 * i]     - mean) * rstd * g0 + b0;
                float o1 = (v[2 * i + 1] - mean) * rstd * g1 + b1;
                __half2 ho = __floats2half2_rn(o0, o1);
                op[i] = *(uint32_t*)&ho;
            }
            *(uint4*)(ht + (long)r * 128 + lane * 4) = o4;
        }
    }
}

// ---------------- heads layer-2: persistent smem weights --------------------
__device__ __forceinline__ void heads2_phase(
    uint32_t* sm, const float* __restrict__ hid,
    float* __restrict__ out, int s, int rowbase)
{
    float* hs = (float*)sm;            // 12 rows x 512 floats (stage0 reuse)
    const float* ws = (const float*)(sm + W2S_W);
    const float* bs = ws + 4864;
    const int tid = threadIdx.x;

    for (int i = tid; i < 12 * 128; i += 256) {
        int rr = i >> 7, c4 = i & 127;
        int r = rowbase + rr;
        float4 val = make_float4(0.f, 0.f, 0.f, 0.f);
        if (r < BNR) val = __ldcg((const float4*)(hid + (long)r * 512) + c4);
        ((float4*)hs)[rr * 128 + c4] = val;
    }
    __syncthreads();

    for (int t = tid; t < 12 * 22; t += 256) {
        int row = t / 22, o = t - row * 22;
        int r = rowbase + row;
        if (r < BNR) {
            const float* w; int hbase, klen;
            if (o < 4)      { w = ws + o * 128;             hbase = 0;   klen = 128; }
            else if (o < 6) { w = ws + 512 + (o - 4) * 128; hbase = 128; klen = 128; }
            else            { w = ws + 768 + (o - 6) * 256; hbase = 256; klen = 256; }
            const float* h = hs + row * 512 + hbase;
            float a = 0.f;
            for (int k = 0; k < klen; ++k) a = fmaf(h[k], w[k], a);
            int b = r / 100, n = r - b * 100;
            out[((b * NSTEPS + s) * 100 + n) * 22 + o] = a + bs[o];
        }
    }
    __syncthreads();
}

// ---------------------------------------------------------------------------
__global__ void __launch_bounds__(256, 1)
persist_kernel(const float* __restrict__ lng, const float* __restrict__ lnb,
               const float* __restrict__ cw2, const float* __restrict__ cb2,
               const float* __restrict__ sw2, const float* __restrict__ sb2,
               const float* __restrict__ lw2, const float* __restrict__ lb2,
               float* __restrict__ out)
{
    extern __shared__ uint32_t sm[];
    float* bS0 = (float*)(sm + BIAS_W);
    float* bS1 = bS0 + 128;
    float* bSh = bS1 + 128;
    float* w2s = (float*)(sm + W2S_W);

    const int tid = threadIdx.x;
    const int cta = blockIdx.x;
    const int mx = cta % MT, ny = cta / MT;
    const int m0  = mx * MROWS;
    const int nb0 = ny * 128;           // gate-row base
    const int j0  = ny * 32;            // j-col base
    const int hn0 = ny * 64;            // heads1 col base
    const int rowbase = m0 + ny * 12;   // LN/heads2 group-local rows (12 each)

    if (tid < 128) { bS0[tid] = g_bre0[nb0 + tid]; bS1[tid] = g_bre1[nb0 + tid]; }
    if (tid < 64)  { bSh[tid] = g_bh1[hn0 + tid]; }
    for (int i = tid; i < 128; i += 256)
        ((float4*)w2s)[i] = __ldg((const float4*)cw2 + i);
    for (int i = tid; i < 64; i += 256)
        ((float4*)(w2s + 512))[i] = __ldg((const float4*)sw2 + i);
    for (int i = tid; i < 1024; i += 256)
        ((float4*)(w2s + 768))[i] = __ldg((const float4*)lw2 + i);
    if (tid < 22) {
        float b;
        if (tid < 4)      b = __ldg(&cb2[tid]);
        else if (tid < 6) b = __ldg(&sb2[tid - 4]);
        else              b = __ldg(&lb2[tid - 6]);
        w2s[4864 + tid] = b;
    }
    __syncthreads();

    float c0r[12], c1r[12];
#pragma unroll
    for (int i = 0; i < 12; ++i) { c0r[i] = 0.f; c1r[i] = 0.f; }

    const uint32_t* W0sl  = g_Wre0 + (long)nb0 * 256;
    const uint32_t* W1sl  = g_Wre1 + (long)nb0 * 256;
    const uint32_t* Wh1sl = g_Wh1 + (long)hn0 * 128;

    // ---------------- encoder (fused: phase t = L0(t)+L1(t-1)) --------------
    cell_phase(sm, g_xw, (long)SEQ * 128, g_h0buf[0],
               W0sl, bS0, c0r, g_h0buf[1], m0, j0);            // L0(0)
    gbar_ns(mx);
    for (int t = 1; t < SEQ; ++t) {
        cell2_phase(sm, g_xw + (long)t * 128, (long)SEQ * 128,
                    g_h0buf[t & 1], g_h1buf[(t + 1) & 1],
                    W0sl, W1sl, bS0, bS1, c0r, c1r,
                    g_h0buf[(t + 1) & 1], g_h1buf[t & 1], m0, j0);
        gbar_ns(mx);
    }
    cell_phase(sm, g_h0buf[0], 128, g_h1buf[1],
               W1sl, bS1, c1r, g_h1buf[0], m0, j0);             // L1(63)
    gbar_ns(mx);
    ln_phase(g_h1buf[0], lng, lnb, g_htw, rowbase);
    gbar(mx);

    // ---------------- decoder ----------------
    for (int s = 0; s < NSTEPS; ++s) {
        phaseA_fused(sm, g_htw, g_h0buf[s & 1], Wh1sl, W0sl, bSh, bS0,
                     c0r, g_h0buf[(s + 1) & 1], g_hid, m0, j0, hn0);
        gbar_ns(mx);
        cell_phase(sm, g_h0buf[(s + 1) & 1], 128, g_h1buf[s & 1],
                   W1sl, bS1, c1r, g_h1buf[(s + 1) & 1], m0, j0);
        heads2_phase(sm, g_hid, out, s, rowbase);
        if (s < NSTEPS - 1) {
            gbar_ns(mx);
            ln_phase(g_h1buf[(s + 1) & 1], lng, lnb, g_htw, rowbase);
            gbar(mx);
        }
    }
}

// ---------------------------------------------------------------------------
extern "C" void kernel_launch(void* const* d_in, const int* in_sizes, int n_in,
                              void* d_out, int out_size)
{
    (void)in_sizes; (void)n_in; (void)out_size;
    const float* x    = (const float*)d_in[0];
    const float* Wih0 = (const float*)d_in[1];
    const float* Whh0 = (const float*)d_in[2];
    const float* bih0 = (const float*)d_in[3];
    const float* bhh0 = (const float*)d_in[4];
    const float* Wih1 = (const float*)d_in[5];
    const float* Whh1 = (const float*)d_in[6];
    const float* bih1 = (const float*)d_in[7];
    const float* bhh1 = (const float*)d_in[8];
    const float* lng  = (const float*)d_in[9];
    const float* lnb  = (const float*)d_in[10];
    const float* cw1  = (const float*)d_in[11];
    const float* cb1  = (const float*)d_in[12];
    const float* cw2  = (const float*)d_in[13];
    const float* cb2  = (const float*)d_in[14];
    const float* sw1  = (const float*)d_in[15];
    const float* sb1  = (const float*)d_in[16];
    const float* sw2  = (const float*)d_in[17];
    const float* sb2  = (const float*)d_in[18];
    const float* lw1  = (const float*)d_in[19];
    const float* lb1  = (const float*)d_in[20];
    const float* lw2  = (const float*)d_in[21];
    const float* lb2  = (const float*)d_in[22];
    float* out = (float*)d_out;

    uint32_t *Wre0, *Wre1;
    float *bre0, *bre1;
    cudaGetSymbolAddress((void**)&Wre0, g_Wre0);
    cudaGetSymbolAddress((void**)&Wre1, g_Wre1);
    cudaGetSymbolAddress((void**)&bre0, g_bre0);
    cudaGetSymbolAddress((void**)&bre1, g_bre1);

    cudaFuncSetAttribute(persist_kernel,
                         cudaFuncAttributeMaxDynamicSharedMemorySize, PSMEM);

    transpose_kernel<<<(BNR * SEQ * 32 + 255) / 256, 256>>>(x);
    rearr_w_kernel<<<1024, 256>>>(Wih0, Whh0, bih0, bhh0, Wre0, bre0);
    rearr_w_kernel<<<1024, 256>>>(Wih1, Whh1, bih1, bhh1, Wre1, bre1);
    rearr_h1_kernel<<<256, 256>>>(cw1, cb1, sw1, sb1, lw1, lb1);
    zero_state_kernel<<<800, 256>>>();

    persist_kernel<<<NCTA, 256, PSMEM>>>(lng, lnb, cw2, cb2, sw2, sb2,
                                         lw2, lb2, out);
}